// round 5
// baseline (speedup 1.0000x reference)
#include <cuda_runtime.h>
#include <cuda_bf16.h>

#define MAXN 50176
#define MAXE 850176

// -------- scratch (device globals; no allocation allowed) --------
__device__ float  g_xl[MAXN * 64];      // lin(x)  [N,64]
__device__ float  g_si[MAXN];           // per-node dst-side logit
__device__ float  g_sj[MAXN];           // per-node src-side logit
__device__ int    g_deg[MAXN];          // in-degree (incl. self loop)
__device__ int    g_rowptr[MAXN + 1];
__device__ int    g_rank[MAXE];         // per-edge rank within dst (1..deg)
__device__ int    g_csrc[MAXE + MAXN];  // CSR src ids (dst-sorted)
__device__ double g_bnsum[128];         // [0:64) sum, [64:128) sumsq

// -------- K1: xl = x @ W^T, per-node attention scalars, + init duties --------
__global__ void k_gemm(const float* __restrict__ x, const float* __restrict__ W,
                       const float* __restrict__ emb,
                       const float* __restrict__ att_i, const float* __restrict__ att_j,
                       const float* __restrict__ att_em_i, const float* __restrict__ att_em_j,
                       int N) {
    __shared__ float2 Wt2[64][32];      // Wt2[k][l] = (W[2l][k], W[2l+1][k])
    int tid = threadIdx.x;
    if (blockIdx.x == 0 && tid < 128) g_bnsum[tid] = 0.0;   // fused init
    for (int s = tid; s < 64 * 32; s += 256) {
        int k = s >> 5, l = s & 31;
        Wt2[k][l] = make_float2(W[(2 * l) * 64 + k], W[(2 * l + 1) * 64 + k]);
    }
    __syncthreads();
    int warp = tid >> 5, lane = tid & 31;
    int c0 = 2 * lane;
    float ai0 = att_i[c0],    ai1 = att_i[c0 + 1];
    float aj0 = att_j[c0],    aj1 = att_j[c0 + 1];
    float e0i = att_em_i[c0], e1i = att_em_i[c0 + 1];
    float e0j = att_em_j[c0], e1j = att_em_j[c0 + 1];

    for (int r = blockIdx.x * 8 + warp; r < N; r += gridDim.x * 8) {
        float xv0 = x[r * 64 + lane];
        float xv1 = x[r * 64 + 32 + lane];
        float a0 = 0.f, a1 = 0.f;
#pragma unroll
        for (int k = 0; k < 32; k++) {
            float xk = __shfl_sync(0xffffffffu, xv0, k);
            float2 w = Wt2[k][lane];
            a0 = fmaf(xk, w.x, a0);
            a1 = fmaf(xk, w.y, a1);
        }
#pragma unroll
        for (int k = 0; k < 32; k++) {
            float xk = __shfl_sync(0xffffffffu, xv1, k);
            float2 w = Wt2[32 + k][lane];
            a0 = fmaf(xk, w.x, a0);
            a1 = fmaf(xk, w.y, a1);
        }
        *(float2*)&g_xl[r * 64 + c0] = make_float2(a0, a1);

        float2 em = *(const float2*)&emb[r * 64 + c0];
        float si = a0 * ai0 + a1 * ai1 + em.x * e0i + em.y * e1i;
        float sj = a0 * aj0 + a1 * aj1 + em.x * e0j + em.y * e1j;
#pragma unroll
        for (int o = 16; o; o >>= 1) {
            si += __shfl_xor_sync(0xffffffffu, si, o);
            sj += __shfl_xor_sync(0xffffffffu, sj, o);
        }
        if (lane == 0) { g_si[r] = si; g_sj[r] = sj; g_deg[r] = 1; }  // fused deg init
    }
}

// -------- K2: degree count + per-edge rank (the only atomic pass) --------
__global__ void k_count(const int* __restrict__ ei, int E) {
    int t = blockIdx.x * blockDim.x + threadIdx.x;
    int E4 = E >> 2;
    if (t < E4) {
        int4 d4 = *(const int4*)&ei[E + 4 * t];
        int4 r4;
        r4.x = atomicAdd(&g_deg[d4.x], 1);
        r4.y = atomicAdd(&g_deg[d4.y], 1);
        r4.z = atomicAdd(&g_deg[d4.z], 1);
        r4.w = atomicAdd(&g_deg[d4.w], 1);
        *(int4*)&g_rank[4 * t] = r4;
    } else {
        int e = 4 * E4 + (t - E4);
        if (e < E) g_rank[e] = atomicAdd(&g_deg[ei[E + e]], 1);
    }
}

// -------- K3: exclusive scan (single block, smem-staged) + self-loop emit --------
__global__ void k_scan(int N) {
    extern __shared__ int sdeg[];                 // N ints (~200 KB)
    __shared__ int wtot[32];
    __shared__ int s_total;
    int tid = threadIdx.x, lane = tid & 31, wid = tid >> 5;

    for (int i = tid; i < N; i += 1024) sdeg[i] = g_deg[i];
    __syncthreads();

    int chunk = (N + 1023) >> 10;
    int beg = tid * chunk;
    int end = beg + chunk; if (end > N) end = N;
    int sum = 0;
    for (int i = beg; i < end; i++) sum += sdeg[i];

    int incl = sum;
#pragma unroll
    for (int d = 1; d < 32; d <<= 1) {
        int t = __shfl_up_sync(0xffffffffu, incl, d);
        if (lane >= d) incl += t;
    }
    if (lane == 31) wtot[wid] = incl;
    __syncthreads();
    if (wid == 0) {
        int s = wtot[lane];
        int si_ = s;
#pragma unroll
        for (int d = 1; d < 32; d <<= 1) {
            int t = __shfl_up_sync(0xffffffffu, si_, d);
            if (lane >= d) si_ += t;
        }
        wtot[lane] = si_ - s;
        if (lane == 31) s_total = si_;
    }
    __syncthreads();
    int excl = wtot[wid] + incl - sum;

    for (int i = beg; i < end; i++) { int v = sdeg[i]; sdeg[i] = excl; excl += v; }
    __syncthreads();

    for (int i = tid; i < N; i += 1024) {
        int p = sdeg[i];
        g_rowptr[i] = p;
        g_csrc[p] = i;                            // self-loop at rank 0
    }
    if (tid == 0) g_rowptr[N] = s_total;
}

// -------- K4: atomic-free scatter via precomputed ranks --------
__global__ void k_scatter(const int* __restrict__ ei, int E) {
    int e = blockIdx.x * blockDim.x + threadIdx.x;
    if (e >= E) return;
    int s = ei[e];
    int d = ei[E + e];
    g_csrc[g_rowptr[d] + g_rank[e]] = s;
}

// -------- K5: two-pass softmax agg: lane-parallel denom (L1 warming) +
//              unroll-4 high-MLP gather-accumulate --------
__global__ void k_agg(const float* __restrict__ bias, float* __restrict__ out, int N) {
    int gwarp = (blockIdx.x * blockDim.x + threadIdx.x) >> 5;
    int lane = threadIdx.x & 31;
    if (gwarp >= N) return;
    int i = gwarp;
    int beg = g_rowptr[i], end = g_rowptr[i + 1];
    float si = g_si[i];
    int c0 = 2 * lane;

    // pass 1: denominator, 32 edges in flight per warp (warms csrc/sj in L1)
    float ssum = 0.f;
    for (int k = beg + lane; k < end; k += 32) {
        int s = g_csrc[k];
        float a = si + g_sj[s];
        a = a >= 0.f ? a : 0.2f * a;
        ssum += __expf(a);
    }
#pragma unroll
    for (int o = 16; o; o >>= 1) ssum += __shfl_xor_sync(0xffffffffu, ssum, o);
    float inv = 1.f / (ssum + 1e-16f);

    // pass 2: unroll-4 — csrc/sj re-reads hit L1; 4 independent xl gathers in flight
    float ax = 0.f, ay = 0.f;
    int k = beg;
    for (; k + 4 <= end; k += 4) {
        int s0 = g_csrc[k],     s1 = g_csrc[k + 1];
        int s2 = g_csrc[k + 2], s3 = g_csrc[k + 3];
        float a0 = si + g_sj[s0], a1 = si + g_sj[s1];
        float a2 = si + g_sj[s2], a3 = si + g_sj[s3];
        a0 = a0 >= 0.f ? a0 : 0.2f * a0;
        a1 = a1 >= 0.f ? a1 : 0.2f * a1;
        a2 = a2 >= 0.f ? a2 : 0.2f * a2;
        a3 = a3 >= 0.f ? a3 : 0.2f * a3;
        float w0 = __expf(a0), w1 = __expf(a1), w2 = __expf(a2), w3 = __expf(a3);
        float2 v0 = *(const float2*)&g_xl[s0 * 64 + c0];
        float2 v1 = *(const float2*)&g_xl[s1 * 64 + c0];
        float2 v2 = *(const float2*)&g_xl[s2 * 64 + c0];
        float2 v3 = *(const float2*)&g_xl[s3 * 64 + c0];
        ax = fmaf(w0, v0.x, ax); ay = fmaf(w0, v0.y, ay);
        ax = fmaf(w1, v1.x, ax); ay = fmaf(w1, v1.y, ay);
        ax = fmaf(w2, v2.x, ax); ay = fmaf(w2, v2.y, ay);
        ax = fmaf(w3, v3.x, ax); ay = fmaf(w3, v3.y, ay);
    }
    for (; k < end; ++k) {
        int s = g_csrc[k];
        float a = si + g_sj[s];
        a = a >= 0.f ? a : 0.2f * a;
        float w = __expf(a);
        float2 v = *(const float2*)&g_xl[s * 64 + c0];
        ax = fmaf(w, v.x, ax);
        ay = fmaf(w, v.y, ay);
    }
    float2 b2 = *(const float2*)&bias[c0];
    *(float2*)&out[i * 64 + c0] = make_float2(fmaf(ax, inv, b2.x), fmaf(ay, inv, b2.y));
}

// -------- K6: BN stats (double partials) --------
__global__ void k_bnred(const float* __restrict__ out, int N) {
    __shared__ double ssum[256], ssq[256];
    int tid = threadIdx.x;
    double s = 0.0, q = 0.0;
    int total = N * 64;
    for (int idx = blockIdx.x * 256 + tid; idx < total; idx += gridDim.x * 256) {
        double v = (double)out[idx];
        s += v; q += v * v;
    }
    ssum[tid] = s; ssq[tid] = q;
    __syncthreads();
    if (tid < 128) { ssum[tid] += ssum[tid + 128]; ssq[tid] += ssq[tid + 128]; }
    __syncthreads();
    if (tid < 64) {
        double S = ssum[tid] + ssum[tid + 64];
        double Q = ssq[tid] + ssq[tid + 64];
        atomicAdd(&g_bnsum[tid], S);
        atomicAdd(&g_bnsum[64 + tid], Q);
    }
}

// -------- K7: apply BN + ReLU (finalize fused per-block) --------
__global__ void k_bnapply(const float* __restrict__ gamma, const float* __restrict__ beta,
                          float* __restrict__ out, int N) {
    __shared__ float s_scale[64], s_shift[64];
    int tid = threadIdx.x;
    if (tid < 64) {
        double mu  = g_bnsum[tid] / (double)N;
        double var = g_bnsum[64 + tid] / (double)N - mu * mu;
        float sc = (float)(rsqrt(var + 1e-5)) * gamma[tid];
        s_scale[tid] = sc;
        s_shift[tid] = fmaf(-(float)mu, sc, beta[tid]);
    }
    __syncthreads();
    int idx = blockIdx.x * blockDim.x + tid;
    if (idx >= N * 64) return;
    int c = idx & 63;
    float v = fmaf(out[idx], s_scale[c], s_shift[c]);
    out[idx] = fmaxf(v, 0.f);
}

extern "C" void kernel_launch(void* const* d_in, const int* in_sizes, int n_in,
                              void* d_out, int out_size) {
    const float* x        = (const float*)d_in[0];
    const int*   ei       = (const int*)d_in[1];
    const float* emb      = (const float*)d_in[2];
    const float* W        = (const float*)d_in[3];
    const float* att_i    = (const float*)d_in[4];
    const float* att_j    = (const float*)d_in[5];
    const float* att_em_i = (const float*)d_in[6];
    const float* att_em_j = (const float*)d_in[7];
    const float* bias     = (const float*)d_in[8];
    const float* gamma    = (const float*)d_in[9];
    const float* beta     = (const float*)d_in[10];
    float* out = (float*)d_out;

    int N = in_sizes[0] / 64;
    int E = in_sizes[1] / 2;

    cudaFuncSetAttribute(k_scan, cudaFuncAttributeMaxDynamicSharedMemorySize, MAXN * 4);
    size_t scan_smem = (size_t)N * 4;

    int E4 = E >> 2;
    int cnt_threads = E4 + (E - 4 * E4);

    k_gemm<<<1480, 256>>>(x, W, emb, att_i, att_j, att_em_i, att_em_j, N);
    k_count<<<(cnt_threads + 255) / 256, 256>>>(ei, E);
    k_scan<<<1, 1024, scan_smem>>>(N);
    k_scatter<<<(E + 255) / 256, 256>>>(ei, E);
    k_agg<<<(N + 7) / 8, 256>>>(bias, out, N);
    k_bnred<<<1184, 256>>>(out, N);
    k_bnapply<<<(N * 64 + 255) / 256, 256>>>(gamma, beta, out, N);
}

// round 6
// speedup vs baseline: 1.1588x; 1.1588x over previous
#include <cuda_runtime.h>
#include <cuda_bf16.h>

#define MAXN 50176
#define MAXE 850176
#define GEMM_BLOCKS 1480

// -------- scratch (device globals; no allocation allowed) --------
__device__ float  g_xl[MAXN * 64];      // lin(x)  [N,64]
__device__ float  g_si[MAXN];           // per-node dst-side logit
__device__ float  g_sj[MAXN];           // per-node src-side logit
__device__ int    g_deg[MAXN];          // in-degree (EXCL self loop; memset to 0)
__device__ float  g_denom[MAXN];        // softmax denominators (memset to 0)
__device__ int    g_rowptr[MAXN + 1];
__device__ int    g_rank[MAXE];         // per-edge rank within dst (0..deg-1)
__device__ int    g_csrc[MAXE + MAXN];  // CSR src ids (dst-sorted)
__device__ float  g_w[MAXE + MAXN];     // per-slot softmax weights (unnormalized)
__device__ double g_bnsum[128];         // [0:64) sum, [64:128) sumsq

// -------- K1: fused [count blocks | gemm blocks] --------
// count: rank[e] = atomicAdd(deg[dst]); gemm: xl = x@W^T + per-node logits.
__global__ void k_gemm_count(const float* __restrict__ x, const float* __restrict__ W,
                             const float* __restrict__ emb,
                             const float* __restrict__ att_i, const float* __restrict__ att_j,
                             const float* __restrict__ att_em_i, const float* __restrict__ att_em_j,
                             const int* __restrict__ ei,
                             int N, int E, int cntBlocks) {
    int tid = threadIdx.x;

    if (blockIdx.x < cntBlocks) {
        // ---- count role (latency-bound; low blockIdx so it launches first) ----
        if (blockIdx.x == 0 && tid < 128) g_bnsum[tid] = 0.0;
        int t = blockIdx.x * 256 + tid;
        int E4 = E >> 2;
        if (t < E4) {
            int4 d4 = *(const int4*)&ei[E + 4 * t];
            int4 r4;
            r4.x = atomicAdd(&g_deg[d4.x], 1);
            r4.y = atomicAdd(&g_deg[d4.y], 1);
            r4.z = atomicAdd(&g_deg[d4.z], 1);
            r4.w = atomicAdd(&g_deg[d4.w], 1);
            *(int4*)&g_rank[4 * t] = r4;
        } else {
            int e = 4 * E4 + (t - E4);
            if (e < E) g_rank[e] = atomicAdd(&g_deg[ei[E + e]], 1);
        }
        return;
    }

    // ---- gemm role ----
    __shared__ float2 Wt2[64][32];      // Wt2[k][l] = (W[2l][k], W[2l+1][k])
    for (int s = tid; s < 64 * 32; s += 256) {
        int k = s >> 5, l = s & 31;
        Wt2[k][l] = make_float2(W[(2 * l) * 64 + k], W[(2 * l + 1) * 64 + k]);
    }
    __syncthreads();
    int vbid = blockIdx.x - cntBlocks;
    int warp = tid >> 5, lane = tid & 31;
    int c0 = 2 * lane;
    float ai0 = att_i[c0],    ai1 = att_i[c0 + 1];
    float aj0 = att_j[c0],    aj1 = att_j[c0 + 1];
    float e0i = att_em_i[c0], e1i = att_em_i[c0 + 1];
    float e0j = att_em_j[c0], e1j = att_em_j[c0 + 1];

    for (int r = vbid * 8 + warp; r < N; r += GEMM_BLOCKS * 8) {
        float xv0 = x[r * 64 + lane];
        float xv1 = x[r * 64 + 32 + lane];
        float a0 = 0.f, a1 = 0.f;
#pragma unroll
        for (int k = 0; k < 32; k++) {
            float xk = __shfl_sync(0xffffffffu, xv0, k);
            float2 w = Wt2[k][lane];
            a0 = fmaf(xk, w.x, a0);
            a1 = fmaf(xk, w.y, a1);
        }
#pragma unroll
        for (int k = 0; k < 32; k++) {
            float xk = __shfl_sync(0xffffffffu, xv1, k);
            float2 w = Wt2[32 + k][lane];
            a0 = fmaf(xk, w.x, a0);
            a1 = fmaf(xk, w.y, a1);
        }
        *(float2*)&g_xl[r * 64 + c0] = make_float2(a0, a1);

        float2 em = *(const float2*)&emb[r * 64 + c0];
        float si = a0 * ai0 + a1 * ai1 + em.x * e0i + em.y * e1i;
        float sj = a0 * aj0 + a1 * aj1 + em.x * e0j + em.y * e1j;
#pragma unroll
        for (int o = 16; o; o >>= 1) {
            si += __shfl_xor_sync(0xffffffffu, si, o);
            sj += __shfl_xor_sync(0xffffffffu, sj, o);
        }
        if (lane == 0) { g_si[r] = si; g_sj[r] = sj; }
    }
}

// -------- K2: exclusive scan over (deg+1), single block, smem-staged --------
__global__ void k_scan(int N) {
    extern __shared__ int sdeg[];                 // N ints (~200 KB)
    __shared__ int wtot[32];
    __shared__ int s_total;
    int tid = threadIdx.x, lane = tid & 31, wid = tid >> 5;

    for (int i = tid; i < N; i += 1024) sdeg[i] = g_deg[i] + 1;   // +1 = self loop
    __syncthreads();

    int chunk = (N + 1023) >> 10;
    int beg = tid * chunk;
    int end = beg + chunk; if (end > N) end = N;
    int sum = 0;
    for (int i = beg; i < end; i++) sum += sdeg[i];

    int incl = sum;
#pragma unroll
    for (int d = 1; d < 32; d <<= 1) {
        int t = __shfl_up_sync(0xffffffffu, incl, d);
        if (lane >= d) incl += t;
    }
    if (lane == 31) wtot[wid] = incl;
    __syncthreads();
    if (wid == 0) {
        int s = wtot[lane];
        int si_ = s;
#pragma unroll
        for (int d = 1; d < 32; d <<= 1) {
            int t = __shfl_up_sync(0xffffffffu, si_, d);
            if (lane >= d) si_ += t;
        }
        wtot[lane] = si_ - s;
        if (lane == 31) s_total = si_;
    }
    __syncthreads();
    int excl = wtot[wid] + incl - sum;

    for (int i = beg; i < end; i++) { int v = sdeg[i]; sdeg[i] = excl; excl += v; }
    __syncthreads();

    for (int i = tid; i < N; i += 1024) g_rowptr[i] = sdeg[i];
    if (tid == 0) g_rowptr[N] = s_total;
}

// -------- K3: scatter edges + self loops; compute w = exp(leaky(si+sj));
//              accumulate denom via spread-address REDG --------
__device__ __forceinline__ void scat_one(int s, int d, int pos) {
    float a = g_si[d] + g_sj[s];
    a = a >= 0.f ? a : 0.2f * a;
    float w = __expf(a);
    g_csrc[pos] = s;
    g_w[pos] = w;
    atomicAdd(&g_denom[d], w);
}

__global__ void k_scatter(const int* __restrict__ ei, int E, int N, int cntThreads) {
    int t = blockIdx.x * blockDim.x + threadIdx.x;
    int E4 = E >> 2;
    if (t < E4) {
        int4 s4 = *(const int4*)&ei[4 * t];
        int4 d4 = *(const int4*)&ei[E + 4 * t];
        int4 r4 = *(const int4*)&g_rank[4 * t];
        scat_one(s4.x, d4.x, g_rowptr[d4.x] + 1 + r4.x);
        scat_one(s4.y, d4.y, g_rowptr[d4.y] + 1 + r4.y);
        scat_one(s4.z, d4.z, g_rowptr[d4.z] + 1 + r4.z);
        scat_one(s4.w, d4.w, g_rowptr[d4.w] + 1 + r4.w);
    } else if (t < cntThreads) {
        int e = 4 * E4 + (t - E4);
        if (e < E) {
            int s = ei[e], d = ei[E + e];
            scat_one(s, d, g_rowptr[d] + 1 + g_rank[e]);
        }
    } else {
        int i = t - cntThreads;                    // self loops at rank 0
        if (i < N) scat_one(i, i, g_rowptr[i]);
    }
}

// -------- K4: agg — pure weighted gather, unroll-4, no MUFU in loop --------
__global__ void k_agg(const float* __restrict__ bias, float* __restrict__ out, int N) {
    int gwarp = (blockIdx.x * blockDim.x + threadIdx.x) >> 5;
    int lane = threadIdx.x & 31;
    if (gwarp >= N) return;
    int i = gwarp;
    int beg = g_rowptr[i], end = g_rowptr[i + 1];
    float inv = 1.f / (g_denom[i] + 1e-16f);
    int c0 = 2 * lane;

    float ax = 0.f, ay = 0.f;
    int k = beg;
    for (; k + 4 <= end; k += 4) {
        int s0 = g_csrc[k],     s1 = g_csrc[k + 1];
        int s2 = g_csrc[k + 2], s3 = g_csrc[k + 3];
        float w0 = g_w[k],     w1 = g_w[k + 1];
        float w2 = g_w[k + 2], w3 = g_w[k + 3];
        float2 v0 = *(const float2*)&g_xl[s0 * 64 + c0];
        float2 v1 = *(const float2*)&g_xl[s1 * 64 + c0];
        float2 v2 = *(const float2*)&g_xl[s2 * 64 + c0];
        float2 v3 = *(const float2*)&g_xl[s3 * 64 + c0];
        ax = fmaf(w0, v0.x, ax); ay = fmaf(w0, v0.y, ay);
        ax = fmaf(w1, v1.x, ax); ay = fmaf(w1, v1.y, ay);
        ax = fmaf(w2, v2.x, ax); ay = fmaf(w2, v2.y, ay);
        ax = fmaf(w3, v3.x, ax); ay = fmaf(w3, v3.y, ay);
    }
    for (; k < end; ++k) {
        int s = g_csrc[k];
        float w = g_w[k];
        float2 v = *(const float2*)&g_xl[s * 64 + c0];
        ax = fmaf(w, v.x, ax);
        ay = fmaf(w, v.y, ay);
    }
    float2 b2 = *(const float2*)&bias[c0];
    *(float2*)&out[i * 64 + c0] = make_float2(fmaf(ax, inv, b2.x), fmaf(ay, inv, b2.y));
}

// -------- K5: BN stats (double partials) --------
__global__ void k_bnred(const float* __restrict__ out, int N) {
    __shared__ double ssum[256], ssq[256];
    int tid = threadIdx.x;
    double s = 0.0, q = 0.0;
    int total = N * 64;
    for (int idx = blockIdx.x * 256 + tid; idx < total; idx += gridDim.x * 256) {
        double v = (double)out[idx];
        s += v; q += v * v;
    }
    ssum[tid] = s; ssq[tid] = q;
    __syncthreads();
    if (tid < 128) { ssum[tid] += ssum[tid + 128]; ssq[tid] += ssq[tid + 128]; }
    __syncthreads();
    if (tid < 64) {
        double S = ssum[tid] + ssum[tid + 64];
        double Q = ssq[tid] + ssq[tid + 64];
        atomicAdd(&g_bnsum[tid], S);
        atomicAdd(&g_bnsum[64 + tid], Q);
    }
}

// -------- K6: apply BN + ReLU (finalize fused per-block) --------
__global__ void k_bnapply(const float* __restrict__ gamma, const float* __restrict__ beta,
                          float* __restrict__ out, int N) {
    __shared__ float s_scale[64], s_shift[64];
    int tid = threadIdx.x;
    if (tid < 64) {
        double mu  = g_bnsum[tid] / (double)N;
        double var = g_bnsum[64 + tid] / (double)N - mu * mu;
        float sc = (float)(rsqrt(var + 1e-5)) * gamma[tid];
        s_scale[tid] = sc;
        s_shift[tid] = fmaf(-(float)mu, sc, beta[tid]);
    }
    __syncthreads();
    int idx = blockIdx.x * blockDim.x + tid;
    if (idx >= N * 64) return;
    int c = idx & 63;
    float v = fmaf(out[idx], s_scale[c], s_shift[c]);
    out[idx] = fmaxf(v, 0.f);
}

extern "C" void kernel_launch(void* const* d_in, const int* in_sizes, int n_in,
                              void* d_out, int out_size) {
    const float* x        = (const float*)d_in[0];
    const int*   ei       = (const int*)d_in[1];
    const float* emb      = (const float*)d_in[2];
    const float* W        = (const float*)d_in[3];
    const float* att_i    = (const float*)d_in[4];
    const float* att_j    = (const float*)d_in[5];
    const float* att_em_i = (const float*)d_in[6];
    const float* att_em_j = (const float*)d_in[7];
    const float* bias     = (const float*)d_in[8];
    const float* gamma    = (const float*)d_in[9];
    const float* beta     = (const float*)d_in[10];
    float* out = (float*)d_out;

    int N = in_sizes[0] / 64;
    int E = in_sizes[1] / 2;

    cudaFuncSetAttribute(k_scan, cudaFuncAttributeMaxDynamicSharedMemorySize, MAXN * 4);
    size_t scan_smem = (size_t)N * 4;

    void* p_deg = nullptr;
    void* p_den = nullptr;
    cudaGetSymbolAddress(&p_deg, g_deg);
    cudaGetSymbolAddress(&p_den, g_denom);
    cudaMemsetAsync(p_deg, 0, (size_t)N * 4);
    cudaMemsetAsync(p_den, 0, (size_t)N * 4);

    int E4 = E >> 2;
    int cntThreads = E4 + (E - 4 * E4);
    int cntBlocks  = (cntThreads + 255) / 256;
    int sctThreads = cntThreads + N;

    k_gemm_count<<<cntBlocks + GEMM_BLOCKS, 256>>>(x, W, emb, att_i, att_j,
                                                   att_em_i, att_em_j, ei, N, E, cntBlocks);
    k_scan<<<1, 1024, scan_smem>>>(N);
    k_scatter<<<(sctThreads + 255) / 256, 256>>>(ei, E, N, cntThreads);
    k_agg<<<(N + 7) / 8, 256>>>(bias, out, N);
    k_bnred<<<1184, 256>>>(out, N);
    k_bnapply<<<(N * 64 + 255) / 256, 256>>>(gamma, beta, out, N);
}

// round 7
// speedup vs baseline: 1.3246x; 1.1430x over previous
#include <cuda_runtime.h>
#include <cuda_bf16.h>

#define MAXN 50176
#define MAXE 850176
#define GEMM_BLOCKS 1480
#define AGG_BLOCKS 1184

// -------- scratch (device globals; zero-initialized at load; each run restores) ----
__device__ float  g_xl[MAXN * 64];      // lin(x)  [N,64]
__device__ float  g_si[MAXN];           // per-node dst-side logit
__device__ float  g_sj[MAXN];           // per-node src-side logit
__device__ int    g_deg[MAXN];          // in-degree excl self loop (zeroed by bnapply)
__device__ float  g_denom[MAXN];        // softmax denominators (zeroed by bnapply)
__device__ int    g_rowptr[MAXN + 1];
__device__ int    g_rank[MAXE];         // per-edge rank within dst (0..deg-1)
__device__ float2 g_epack[MAXE + MAXN]; // (.x = src bits, .y = weight) per CSR slot
__device__ float  g_bnsum[128];         // [0:64) sum, [64:128) sumsq (zeroed in K1)

// -------- K1: fused [count blocks | gemm blocks] --------
__global__ void k_gemm_count(const float* __restrict__ x, const float* __restrict__ W,
                             const float* __restrict__ emb,
                             const float* __restrict__ att_i, const float* __restrict__ att_j,
                             const float* __restrict__ att_em_i, const float* __restrict__ att_em_j,
                             const int* __restrict__ ei,
                             int N, int E, int cntBlocks) {
    int tid = threadIdx.x;

    if (blockIdx.x < cntBlocks) {
        // ---- count role: rank[e] = fetch-and-add on deg[dst] ----
        if (blockIdx.x == 0 && tid < 128) g_bnsum[tid] = 0.f;
        int t = blockIdx.x * 256 + tid;
        int E4 = E >> 2;
        if (t < E4) {
            int4 d4 = *(const int4*)&ei[E + 4 * t];
            int4 r4;
            r4.x = atomicAdd(&g_deg[d4.x], 1);
            r4.y = atomicAdd(&g_deg[d4.y], 1);
            r4.z = atomicAdd(&g_deg[d4.z], 1);
            r4.w = atomicAdd(&g_deg[d4.w], 1);
            *(int4*)&g_rank[4 * t] = r4;
        } else {
            int e = 4 * E4 + (t - E4);
            if (e < E) g_rank[e] = atomicAdd(&g_deg[ei[E + e]], 1);
        }
        return;
    }

    // ---- gemm role: xl = x @ W^T + per-node logits ----
    __shared__ float2 Wt2[64][32];
    for (int s = tid; s < 64 * 32; s += 256) {
        int k = s >> 5, l = s & 31;
        Wt2[k][l] = make_float2(W[(2 * l) * 64 + k], W[(2 * l + 1) * 64 + k]);
    }
    __syncthreads();
    int vbid = blockIdx.x - cntBlocks;
    int warp = tid >> 5, lane = tid & 31;
    int c0 = 2 * lane;
    float ai0 = att_i[c0],    ai1 = att_i[c0 + 1];
    float aj0 = att_j[c0],    aj1 = att_j[c0 + 1];
    float e0i = att_em_i[c0], e1i = att_em_i[c0 + 1];
    float e0j = att_em_j[c0], e1j = att_em_j[c0 + 1];

    for (int r = vbid * 8 + warp; r < N; r += GEMM_BLOCKS * 8) {
        float xv0 = x[r * 64 + lane];
        float xv1 = x[r * 64 + 32 + lane];
        float a0 = 0.f, a1 = 0.f;
#pragma unroll
        for (int k = 0; k < 32; k++) {
            float xk = __shfl_sync(0xffffffffu, xv0, k);
            float2 w = Wt2[k][lane];
            a0 = fmaf(xk, w.x, a0);
            a1 = fmaf(xk, w.y, a1);
        }
#pragma unroll
        for (int k = 0; k < 32; k++) {
            float xk = __shfl_sync(0xffffffffu, xv1, k);
            float2 w = Wt2[32 + k][lane];
            a0 = fmaf(xk, w.x, a0);
            a1 = fmaf(xk, w.y, a1);
        }
        *(float2*)&g_xl[r * 64 + c0] = make_float2(a0, a1);

        float2 em = *(const float2*)&emb[r * 64 + c0];
        float si = a0 * ai0 + a1 * ai1 + em.x * e0i + em.y * e1i;
        float sj = a0 * aj0 + a1 * aj1 + em.x * e0j + em.y * e1j;
#pragma unroll
        for (int o = 16; o; o >>= 1) {
            si += __shfl_xor_sync(0xffffffffu, si, o);
            sj += __shfl_xor_sync(0xffffffffu, sj, o);
        }
        if (lane == 0) { g_si[r] = si; g_sj[r] = sj; }
    }
}

// -------- K2: exclusive scan over (deg+1), single block, smem-staged --------
__global__ void k_scan(int N) {
    extern __shared__ int sdeg[];
    __shared__ int wtot[32];
    __shared__ int s_total;
    int tid = threadIdx.x, lane = tid & 31, wid = tid >> 5;

    for (int i = tid; i < N; i += 1024) sdeg[i] = g_deg[i] + 1;   // +1 = self loop
    __syncthreads();

    int chunk = (N + 1023) >> 10;
    int beg = tid * chunk;
    int end = beg + chunk; if (end > N) end = N;
    int sum = 0;
    for (int i = beg; i < end; i++) sum += sdeg[i];

    int incl = sum;
#pragma unroll
    for (int d = 1; d < 32; d <<= 1) {
        int t = __shfl_up_sync(0xffffffffu, incl, d);
        if (lane >= d) incl += t;
    }
    if (lane == 31) wtot[wid] = incl;
    __syncthreads();
    if (wid == 0) {
        int s = wtot[lane];
        int si_ = s;
#pragma unroll
        for (int d = 1; d < 32; d <<= 1) {
            int t = __shfl_up_sync(0xffffffffu, si_, d);
            if (lane >= d) si_ += t;
        }
        wtot[lane] = si_ - s;
        if (lane == 31) s_total = si_;
    }
    __syncthreads();
    int excl = wtot[wid] + incl - sum;

    for (int i = beg; i < end; i++) { int v = sdeg[i]; sdeg[i] = excl; excl += v; }
    __syncthreads();

    for (int i = tid; i < N; i += 1024) g_rowptr[i] = sdeg[i];
    if (tid == 0) g_rowptr[N] = s_total;
}

// -------- K3: scatter edges + self loops; w = exp(leaky(si+sj)); denom REDG ------
__device__ __forceinline__ void scat_one(int s, int d, int pos) {
    float a = g_si[d] + g_sj[s];
    a = a >= 0.f ? a : 0.2f * a;
    float w = __expf(a);
    g_epack[pos] = make_float2(__int_as_float(s), w);
    atomicAdd(&g_denom[d], w);
}

__global__ void k_scatter(const int* __restrict__ ei, int E, int N, int cntThreads) {
    int t = blockIdx.x * blockDim.x + threadIdx.x;
    int E4 = E >> 2;
    if (t < E4) {
        int4 s4 = *(const int4*)&ei[4 * t];
        int4 d4 = *(const int4*)&ei[E + 4 * t];
        int4 r4 = *(const int4*)&g_rank[4 * t];
        scat_one(s4.x, d4.x, g_rowptr[d4.x] + 1 + r4.x);
        scat_one(s4.y, d4.y, g_rowptr[d4.y] + 1 + r4.y);
        scat_one(s4.z, d4.z, g_rowptr[d4.z] + 1 + r4.z);
        scat_one(s4.w, d4.w, g_rowptr[d4.w] + 1 + r4.w);
    } else if (t < cntThreads) {
        int e = 4 * E4 + (t - E4);
        if (e < E) {
            int s = ei[e], d = ei[E + e];
            scat_one(s, d, g_rowptr[d] + 1 + g_rank[e]);
        }
    } else {
        int i = t - cntThreads;                    // self loops at rank 0
        if (i < N) scat_one(i, i, g_rowptr[i]);
    }
}

// -------- K4: persistent agg — packed-edge weighted gather + fused BN stats ------
__global__ void k_agg(const float* __restrict__ bias, float* __restrict__ out, int N) {
    __shared__ float sred[128];
    int tid = threadIdx.x, warp = tid >> 5, lane = tid & 31;
    if (tid < 128) sred[tid] = 0.f;
    __syncthreads();

    int c0 = 2 * lane;
    float2 b2 = *(const float2*)&bias[c0];
    float p0 = 0.f, p1 = 0.f, q0 = 0.f, q1 = 0.f;   // BN partials (few nodes/thread)

    for (int i = blockIdx.x * 8 + warp; i < N; i += AGG_BLOCKS * 8) {
        int beg = g_rowptr[i], end = g_rowptr[i + 1];
        float inv = 1.f / (g_denom[i] + 1e-16f);
        float ax = 0.f, ay = 0.f;

        int k = beg;
        for (; k + 4 <= end; k += 4) {
            float2 e0 = g_epack[k],     e1 = g_epack[k + 1];
            float2 e2 = g_epack[k + 2], e3 = g_epack[k + 3];
            int s0 = __float_as_int(e0.x), s1 = __float_as_int(e1.x);
            int s2 = __float_as_int(e2.x), s3 = __float_as_int(e3.x);
            float2 v0 = *(const float2*)&g_xl[s0 * 64 + c0];
            float2 v1 = *(const float2*)&g_xl[s1 * 64 + c0];
            float2 v2 = *(const float2*)&g_xl[s2 * 64 + c0];
            float2 v3 = *(const float2*)&g_xl[s3 * 64 + c0];
            ax = fmaf(e0.y, v0.x, ax); ay = fmaf(e0.y, v0.y, ay);
            ax = fmaf(e1.y, v1.x, ax); ay = fmaf(e1.y, v1.y, ay);
            ax = fmaf(e2.y, v2.x, ax); ay = fmaf(e2.y, v2.y, ay);
            ax = fmaf(e3.y, v3.x, ax); ay = fmaf(e3.y, v3.y, ay);
        }
        for (; k < end; ++k) {
            float2 e = g_epack[k];
            int s = __float_as_int(e.x);
            float2 v = *(const float2*)&g_xl[s * 64 + c0];
            ax = fmaf(e.y, v.x, ax);
            ay = fmaf(e.y, v.y, ay);
        }
        float ox = fmaf(ax, inv, b2.x);
        float oy = fmaf(ay, inv, b2.y);
        *(float2*)&out[i * 64 + c0] = make_float2(ox, oy);
        p0 += ox; q0 = fmaf(ox, ox, q0);
        p1 += oy; q1 = fmaf(oy, oy, q1);
    }

    atomicAdd(&sred[c0],          p0);
    atomicAdd(&sred[c0 + 1],      p1);
    atomicAdd(&sred[64 + c0],     q0);
    atomicAdd(&sred[64 + c0 + 1], q1);
    __syncthreads();
    if (tid < 128) atomicAdd(&g_bnsum[tid], sred[tid]);
}

// -------- K5: apply BN + ReLU; restore deg/denom to zero for next run ----------
__global__ void k_bnapply(const float* __restrict__ gamma, const float* __restrict__ beta,
                          float* __restrict__ out, int N) {
    __shared__ float s_scale[64], s_shift[64];
    int tid = threadIdx.x;
    if (tid < 64) {
        double mu  = (double)g_bnsum[tid] / (double)N;
        double var = (double)g_bnsum[64 + tid] / (double)N - mu * mu;
        float sc = (float)rsqrt(var + 1e-5) * gamma[tid];
        s_scale[tid] = sc;
        s_shift[tid] = fmaf(-(float)mu, sc, beta[tid]);
    }
    __syncthreads();
    int idx = blockIdx.x * blockDim.x + tid;
    if (idx < N) { g_deg[idx] = 0; g_denom[idx] = 0.f; }   // re-init for next run
    if (idx >= N * 64) return;
    int c = idx & 63;
    float v = fmaf(out[idx], s_scale[c], s_shift[c]);
    out[idx] = fmaxf(v, 0.f);
}

extern "C" void kernel_launch(void* const* d_in, const int* in_sizes, int n_in,
                              void* d_out, int out_size) {
    const float* x        = (const float*)d_in[0];
    const int*   ei       = (const int*)d_in[1];
    const float* emb      = (const float*)d_in[2];
    const float* W        = (const float*)d_in[3];
    const float* att_i    = (const float*)d_in[4];
    const float* att_j    = (const float*)d_in[5];
    const float* att_em_i = (const float*)d_in[6];
    const float* att_em_j = (const float*)d_in[7];
    const float* bias     = (const float*)d_in[8];
    const float* gamma    = (const float*)d_in[9];
    const float* beta     = (const float*)d_in[10];
    float* out = (float*)d_out;

    int N = in_sizes[0] / 64;
    int E = in_sizes[1] / 2;

    cudaFuncSetAttribute(k_scan, cudaFuncAttributeMaxDynamicSharedMemorySize, MAXN * 4);
    size_t scan_smem = (size_t)N * 4;

    int E4 = E >> 2;
    int cntThreads = E4 + (E - 4 * E4);
    int cntBlocks  = (cntThreads + 255) / 256;
    int sctThreads = cntThreads + N;

    k_gemm_count<<<cntBlocks + GEMM_BLOCKS, 256>>>(x, W, emb, att_i, att_j,
                                                   att_em_i, att_em_j, ei, N, E, cntBlocks);
    k_scan<<<1, 1024, scan_smem>>>(N);
    k_scatter<<<(sctThreads + 255) / 256, 256>>>(ei, E, N, cntThreads);
    k_agg<<<AGG_BLOCKS, 256>>>(bias, out, N);
    k_bnapply<<<(N * 64 + 255) / 256, 256>>>(gamma, beta, out, N);
}

// round 8
// speedup vs baseline: 1.8642x; 1.4074x over previous
#include <cuda_runtime.h>

#define MAXN 50176
#define MAXE 850176
#define GRID 888              // 148 SMs x 6 blocks: co-resident on B300(148)/GB300(152)
#define CTA  256
#define NWARP 8

// -------- scratch (device globals; zero at load; each replay self-restores) --------
__device__ float  g_xl[MAXN * 64];
__device__ float  g_si[MAXN];
__device__ float  g_sj[MAXN];
__device__ int    g_deg[MAXN];          // reset in P3
__device__ float  g_denom[MAXN];        // reset in P5
__device__ int    g_rowptr[MAXN + 1];
__device__ int    g_rank[MAXE];
__device__ float2 g_epack[MAXE + MAXN]; // (.x = src bits, .y = weight)
__device__ float  g_bnsum[128];         // reset by block 0 at end
__device__ int    g_bpart[GRID];
__device__ unsigned long long g_bar;    // monotonic ticket counter (never reset)

struct ScanS { int vals[128]; int wred[NWARP]; int off; };
union SmemU {
    float2 Wt2[64][32];                 // 16 KB (P0 gemm)
    ScanS  scan;                        // P1/P2
    float  sred[128];                   // P4 BN partials
    float  bnss[128];                   // P5 scale[0:64) shift[64:128)
};

// Grid-wide barrier: ticket scheme. Increments are grouped per phase because no
// block can pass barrier k until all blocks incremented barrier k.
__device__ __forceinline__ void grid_barrier() {
    __syncthreads();
    if (threadIdx.x == 0) {
        __threadfence();
        unsigned long long t = atomicAdd(&g_bar, 1ULL);
        unsigned long long target = t - (t % GRID) + GRID;
        while (*(volatile unsigned long long*)&g_bar < target) __nanosleep(64);
    }
    __syncthreads();
}

__device__ __forceinline__ void scat_one(int s, int d, int pos) {
    float a = g_si[d] + g_sj[s];
    a = a >= 0.f ? a : 0.2f * a;
    float w = __expf(a);
    g_epack[pos] = make_float2(__int_as_float(s), w);
    atomicAdd(&g_denom[d], w);
}

__global__ void __launch_bounds__(CTA, 6) k_fused(
    const float* __restrict__ x, const int* __restrict__ ei,
    const float* __restrict__ emb, const float* __restrict__ W,
    const float* __restrict__ att_i, const float* __restrict__ att_j,
    const float* __restrict__ att_em_i, const float* __restrict__ att_em_j,
    const float* __restrict__ bias, const float* __restrict__ gamma,
    const float* __restrict__ beta, float* __restrict__ out,
    int N, int E)
{
    __shared__ SmemU sm;
    const int tid = threadIdx.x, bid = blockIdx.x;
    const int lane = tid & 31, wid = tid >> 5;
    const int gtid = bid * CTA + tid;
    const int GT = GRID * CTA;
    const int E4 = E >> 2;

    // ================= P0: count(+rank)  ||  gemm + logits =================
    for (int s = tid; s < 2048; s += CTA) {
        int k = s >> 5, l = s & 31;
        sm.Wt2[k][l] = make_float2(W[(2 * l) * 64 + k], W[(2 * l + 1) * 64 + k]);
    }
    __syncthreads();

    for (int t = gtid; t < E4; t += GT) {
        int4 d4 = *(const int4*)&ei[E + 4 * t];
        int4 r4;
        r4.x = atomicAdd(&g_deg[d4.x], 1);
        r4.y = atomicAdd(&g_deg[d4.y], 1);
        r4.z = atomicAdd(&g_deg[d4.z], 1);
        r4.w = atomicAdd(&g_deg[d4.w], 1);
        *(int4*)&g_rank[4 * t] = r4;
    }
    for (int e = 4 * E4 + gtid; e < E; e += GT)
        g_rank[e] = atomicAdd(&g_deg[ei[E + e]], 1);

    {
        int c0 = 2 * lane;
        float ai0 = att_i[c0],    ai1 = att_i[c0 + 1];
        float aj0 = att_j[c0],    aj1 = att_j[c0 + 1];
        float e0i = att_em_i[c0], e1i = att_em_i[c0 + 1];
        float e0j = att_em_j[c0], e1j = att_em_j[c0 + 1];
        for (int r = bid * NWARP + wid; r < N; r += GRID * NWARP) {
            float xv0 = x[r * 64 + lane];
            float xv1 = x[r * 64 + 32 + lane];
            float a0 = 0.f, a1 = 0.f;
#pragma unroll
            for (int k = 0; k < 32; k++) {
                float xk = __shfl_sync(0xffffffffu, xv0, k);
                float2 w = sm.Wt2[k][lane];
                a0 = fmaf(xk, w.x, a0);
                a1 = fmaf(xk, w.y, a1);
            }
#pragma unroll
            for (int k = 0; k < 32; k++) {
                float xk = __shfl_sync(0xffffffffu, xv1, k);
                float2 w = sm.Wt2[32 + k][lane];
                a0 = fmaf(xk, w.x, a0);
                a1 = fmaf(xk, w.y, a1);
            }
            *(float2*)&g_xl[r * 64 + c0] = make_float2(a0, a1);

            float2 em = *(const float2*)&emb[r * 64 + c0];
            float si = a0 * ai0 + a1 * ai1 + em.x * e0i + em.y * e1i;
            float sj = a0 * aj0 + a1 * aj1 + em.x * e0j + em.y * e1j;
#pragma unroll
            for (int o = 16; o; o >>= 1) {
                si += __shfl_xor_sync(0xffffffffu, si, o);
                sj += __shfl_xor_sync(0xffffffffu, sj, o);
            }
            if (lane == 0) { g_si[r] = si; g_sj[r] = sj; }
        }
    }
    grid_barrier();

    // ================= P1: per-block partial sums of (deg+1) ===============
    const int CH = (N + GRID - 1) / GRID;        // 57 for N=50000 (<=128 required)
    int beg = bid * CH;
    int cnt = N - beg; if (cnt < 0) cnt = 0; if (cnt > CH) cnt = CH;
    {
        int v = (tid < cnt) ? (g_deg[beg + tid] + 1) : 0;
#pragma unroll
        for (int o = 16; o; o >>= 1) v += __shfl_xor_sync(0xffffffffu, v, o);
        if (lane == 0) sm.scan.wred[wid] = v;
        __syncthreads();
        if (tid == 0) {
            int s = 0;
#pragma unroll
            for (int w2 = 0; w2 < NWARP; w2++) s += sm.scan.wred[w2];
            g_bpart[bid] = s;
        }
    }
    grid_barrier();

    // ================= P2: block prefix + local scan -> rowptr =============
    {
        int part = 0;
        for (int j = tid; j < bid; j += CTA) part += g_bpart[j];
#pragma unroll
        for (int o = 16; o; o >>= 1) part += __shfl_xor_sync(0xffffffffu, part, o);
        if (lane == 0) sm.scan.wred[wid] = part;
        __syncthreads();
        if (tid == 0) {
            int s = 0;
#pragma unroll
            for (int w2 = 0; w2 < NWARP; w2++) s += sm.scan.wred[w2];
            sm.scan.off = s;
            if (bid == GRID - 1) g_rowptr[N] = s + g_bpart[bid];
        }
        if (tid < 128) sm.scan.vals[tid] = 0;
        __syncthreads();
        int myv = 0;
        if (tid < cnt) { myv = g_deg[beg + tid] + 1; sm.scan.vals[tid] = myv; }
        __syncthreads();
#pragma unroll
        for (int d = 1; d < 128; d <<= 1) {
            int add = (tid < 128 && tid >= d) ? sm.scan.vals[tid - d] : 0;
            __syncthreads();
            if (tid < 128) sm.scan.vals[tid] += add;
            __syncthreads();
        }
        if (tid < cnt)
            g_rowptr[beg + tid] = sm.scan.off + sm.scan.vals[tid] - myv;
    }
    grid_barrier();

    // ================= P3: scatter + self loops + deg reset ================
    for (int t = gtid; t < E4; t += GT) {
        int4 s4 = *(const int4*)&ei[4 * t];
        int4 d4 = *(const int4*)&ei[E + 4 * t];
        int4 r4 = *(const int4*)&g_rank[4 * t];
        scat_one(s4.x, d4.x, g_rowptr[d4.x] + 1 + r4.x);
        scat_one(s4.y, d4.y, g_rowptr[d4.y] + 1 + r4.y);
        scat_one(s4.z, d4.z, g_rowptr[d4.z] + 1 + r4.z);
        scat_one(s4.w, d4.w, g_rowptr[d4.w] + 1 + r4.w);
    }
    for (int e = 4 * E4 + gtid; e < E; e += GT) {
        int s = ei[e], d = ei[E + e];
        scat_one(s, d, g_rowptr[d] + 1 + g_rank[e]);
    }
    for (int i = gtid; i < N; i += GT) {
        float a = g_si[i] + g_sj[i];               // self loop (rank 0)
        a = a >= 0.f ? a : 0.2f * a;
        float w = __expf(a);
        g_epack[g_rowptr[i]] = make_float2(__int_as_float(i), w);
        atomicAdd(&g_denom[i], w);
        g_deg[i] = 0;                              // restore for next replay
    }
    grid_barrier();

    // ================= P4: weighted gather + fused BN stats ================
    if (tid < 128) sm.sred[tid] = 0.f;
    __syncthreads();
    {
        int c0 = 2 * lane;
        float2 b2 = *(const float2*)&bias[c0];
        float p0 = 0.f, p1 = 0.f, q0 = 0.f, q1 = 0.f;

        for (int i = bid * NWARP + wid; i < N; i += GRID * NWARP) {
            int kb = g_rowptr[i], ke = g_rowptr[i + 1];
            float inv = 1.f / (g_denom[i] + 1e-16f);
            float ax = 0.f, ay = 0.f;
            int k = kb;
            for (; k + 4 <= ke; k += 4) {
                float2 e0 = g_epack[k],     e1 = g_epack[k + 1];
                float2 e2 = g_epack[k + 2], e3 = g_epack[k + 3];
                int s0 = __float_as_int(e0.x), s1 = __float_as_int(e1.x);
                int s2 = __float_as_int(e2.x), s3 = __float_as_int(e3.x);
                float2 v0 = *(const float2*)&g_xl[s0 * 64 + c0];
                float2 v1 = *(const float2*)&g_xl[s1 * 64 + c0];
                float2 v2 = *(const float2*)&g_xl[s2 * 64 + c0];
                float2 v3 = *(const float2*)&g_xl[s3 * 64 + c0];
                ax = fmaf(e0.y, v0.x, ax); ay = fmaf(e0.y, v0.y, ay);
                ax = fmaf(e1.y, v1.x, ax); ay = fmaf(e1.y, v1.y, ay);
                ax = fmaf(e2.y, v2.x, ax); ay = fmaf(e2.y, v2.y, ay);
                ax = fmaf(e3.y, v3.x, ax); ay = fmaf(e3.y, v3.y, ay);
            }
            for (; k < ke; ++k) {
                float2 e = g_epack[k];
                int s = __float_as_int(e.x);
                float2 v = *(const float2*)&g_xl[s * 64 + c0];
                ax = fmaf(e.y, v.x, ax);
                ay = fmaf(e.y, v.y, ay);
            }
            float ox = fmaf(ax, inv, b2.x);
            float oy = fmaf(ay, inv, b2.y);
            *(float2*)&out[i * 64 + c0] = make_float2(ox, oy);
            p0 += ox; q0 = fmaf(ox, ox, q0);
            p1 += oy; q1 = fmaf(oy, oy, q1);
        }
        atomicAdd(&sm.sred[c0],          p0);
        atomicAdd(&sm.sred[c0 + 1],      p1);
        atomicAdd(&sm.sred[64 + c0],     q0);
        atomicAdd(&sm.sred[64 + c0 + 1], q1);
    }
    __syncthreads();
    if (tid < 128) atomicAdd(&g_bnsum[tid], sm.sred[tid]);
    grid_barrier();

    // ================= P5: BN apply + ReLU; denom reset ====================
    if (tid < 64) {
        double mu  = (double)g_bnsum[tid] / (double)N;
        double var = (double)g_bnsum[64 + tid] / (double)N - mu * mu;
        float sc = (float)rsqrt(var + 1e-5) * gamma[tid];
        sm.bnss[tid]      = sc;
        sm.bnss[64 + tid] = fmaf(-(float)mu, sc, beta[tid]);
    }
    __syncthreads();
    {
        int NV = N * 16;                           // float4 elements
        for (int v = gtid; v < NV; v += GT) {
            float4 o4 = *(float4*)(out + v * 4);
            int c0 = (v & 15) * 4;
            o4.x = fmaxf(fmaf(o4.x, sm.bnss[c0],     sm.bnss[64 + c0]),     0.f);
            o4.y = fmaxf(fmaf(o4.y, sm.bnss[c0 + 1], sm.bnss[64 + c0 + 1]), 0.f);
            o4.z = fmaxf(fmaf(o4.z, sm.bnss[c0 + 2], sm.bnss[64 + c0 + 2]), 0.f);
            o4.w = fmaxf(fmaf(o4.w, sm.bnss[c0 + 3], sm.bnss[64 + c0 + 3]), 0.f);
            *(float4*)(out + v * 4) = o4;
        }
        for (int i = gtid; i < N; i += GT) g_denom[i] = 0.f;
    }

    // final barrier: arrive-all; block 0 waits then resets g_bnsum
    __syncthreads();
    if (tid == 0) {
        __threadfence();
        unsigned long long t = atomicAdd(&g_bar, 1ULL);
        if (bid == 0) {
            unsigned long long target = t - (t % GRID) + GRID;
            while (*(volatile unsigned long long*)&g_bar < target) __nanosleep(64);
        }
    }
    __syncthreads();
    if (bid == 0 && tid < 128) g_bnsum[tid] = 0.f;
}

extern "C" void kernel_launch(void* const* d_in, const int* in_sizes, int n_in,
                              void* d_out, int out_size) {
    const float* x        = (const float*)d_in[0];
    const int*   ei       = (const int*)d_in[1];
    const float* emb      = (const float*)d_in[2];
    const float* W        = (const float*)d_in[3];
    const float* att_i    = (const float*)d_in[4];
    const float* att_j    = (const float*)d_in[5];
    const float* att_em_i = (const float*)d_in[6];
    const float* att_em_j = (const float*)d_in[7];
    const float* bias     = (const float*)d_in[8];
    const float* gamma    = (const float*)d_in[9];
    const float* beta     = (const float*)d_in[10];
    float* out = (float*)d_out;

    int N = in_sizes[0] / 64;
    int E = in_sizes[1] / 2;

    k_fused<<<GRID, CTA>>>(x, ei, emb, W, att_i, att_j, att_em_i, att_em_j,
                           bias, gamma, beta, out, N, E);
}